// round 16
// baseline (speedup 1.0000x reference)
#include <cuda_runtime.h>
#include <cuda_fp16.h>
#include <cstdint>

#define SEQ   4096
#define DIN   512
#define HEADS 8
#define DHEAD 64

// Q pre-scale: (1/sqrt(64)) * log2(e)  ->  P = exp2(S)
#define QSCALE 0.1803368801111204f

// ---------------------------------------------------------------------------
// Scratch (__device__ globals; no allocation allowed)
// ---------------------------------------------------------------------------
__device__ __half g_Xh   [SEQ * DIN];             // x cast to fp16
__device__ __half g_Qh   [HEADS * SEQ * DHEAD];   // [h][s][d], pre-scaled by QSCALE
__device__ __half g_Kh   [HEADS * SEQ * DHEAD];   // [h][s][d]
__device__ __half g_Vth  [HEADS * DHEAD * SEQ];   // [h][d][s] transposed
__device__ __half g_Ah   [SEQ * DIN];             // attn out fp16, [s][h*64+v]
__device__ __half g_Wqkvt[3 * DIN * DIN];         // [z][n][k] transposed weights
__device__ __half g_Wot  [DIN * DIN];             // [n][k] transposed Wo

// m16n8k16 HMMA, fp32 accum
__device__ __forceinline__ void mma16816(float c[4],
                                         uint32_t a0, uint32_t a1, uint32_t a2, uint32_t a3,
                                         uint32_t b0, uint32_t b1)
{
    asm volatile(
        "mma.sync.aligned.m16n8k16.row.col.f32.f16.f16.f32 "
        "{%0,%1,%2,%3}, {%4,%5,%6,%7}, {%8,%9}, {%0,%1,%2,%3};"
        : "+f"(c[0]), "+f"(c[1]), "+f"(c[2]), "+f"(c[3])
        : "r"(a0), "r"(a1), "r"(a2), "r"(a3), "r"(b0), "r"(b1));
}

// m16n8k16 HMMA, fp16 accum; C = {c0: row g, c1: row g+8}
__device__ __forceinline__ void mma16816_f16(uint32_t& c0, uint32_t& c1,
                                             uint32_t a0, uint32_t a1, uint32_t a2, uint32_t a3,
                                             uint32_t b0, uint32_t b1)
{
    asm volatile(
        "mma.sync.aligned.m16n8k16.row.col.f16.f16.f16.f16 "
        "{%0,%1}, {%2,%3,%4,%5}, {%6,%7}, {%0,%1};"
        : "+r"(c0), "+r"(c1)
        : "r"(a0), "r"(a1), "r"(a2), "r"(a3), "r"(b0), "r"(b1));
}

__device__ __forceinline__ void ldsm_x4(uint32_t addr,
                                        uint32_t& r0, uint32_t& r1,
                                        uint32_t& r2, uint32_t& r3)
{
    asm volatile("ldmatrix.sync.aligned.m8n8.x4.shared.b16 {%0,%1,%2,%3}, [%4];"
                 : "=r"(r0), "=r"(r1), "=r"(r2), "=r"(r3) : "r"(addr));
}

__device__ __forceinline__ uint32_t smem_u32(const void* p) {
    uint32_t a;
    asm("{ .reg .u64 t; cvta.to.shared.u64 t, %1; cvt.u32.u64 %0, t; }"
        : "=r"(a) : "l"(p));
    return a;
}
__device__ __forceinline__ void cp16(uint32_t dst, const void* src) {
    asm volatile("cp.async.cg.shared.global [%0], [%1], 16;"
                 :: "r"(dst), "l"(src) : "memory");
}
#define CP_COMMIT() asm volatile("cp.async.commit_group;" ::: "memory")
#define CP_WAIT0()  asm volatile("cp.async.wait_group 0;" ::: "memory")
#define CP_WAIT1()  asm volatile("cp.async.wait_group 1;" ::: "memory")

// ---------------------------------------------------------------------------
// x -> fp16 cast
// ---------------------------------------------------------------------------
__global__ __launch_bounds__(256) void xcast_kernel(const float* __restrict__ x)
{
    int idx = (blockIdx.x * 256 + threadIdx.x) * 4;
    float4 v = *(const float4*)(x + idx);
    __half2 h0 = __floats2half2_rn(v.x, v.y);
    __half2 h1 = __floats2half2_rn(v.z, v.w);
    uint2 u; u.x = *(uint32_t*)&h0; u.y = *(uint32_t*)&h1;
    *(uint2*)&g_Xh[idx] = u;
}

// ---------------------------------------------------------------------------
// Prep: cast+transpose weights. z=0/1/2 -> Wq/Wk/Wv -> g_Wqkvt[z][n][k];
// z=3 -> Wo -> g_Wot[n][k].
// ---------------------------------------------------------------------------
__global__ __launch_bounds__(256) void wtrans_kernel(
    const float* __restrict__ Wq, const float* __restrict__ Wk,
    const float* __restrict__ Wv, const float* __restrict__ Wo)
{
    __shared__ float t[64][65];
    const int tid = threadIdx.x;
    const int k0  = blockIdx.x * 64;
    const int n0  = blockIdx.y * 64;
    const int z   = blockIdx.z;
    const float* W = (z == 0) ? Wq : (z == 1) ? Wk : (z == 2) ? Wv : Wo;

    #pragma unroll
    for (int i = 0; i < 16; i++) {
        int idx = tid + i * 256;
        int kk = idx >> 6, nn = idx & 63;
        float v;
        if (z < 3) v = W[(size_t)(n0 >> 6) * (DIN * DHEAD) + (size_t)(k0 + kk) * DHEAD + nn];
        else       v = W[(size_t)(k0 + kk) * DIN + n0 + nn];
        t[kk][nn] = v;
    }
    __syncthreads();

    __half* dst = (z < 3) ? (g_Wqkvt + (size_t)z * DIN * DIN) : g_Wot;
    #pragma unroll
    for (int i = 0; i < 8; i++) {
        int idx = tid + i * 256;
        int nn  = idx >> 5;
        int kk2 = (idx & 31) * 2;
        __half2 p = __floats2half2_rn(t[kk2][nn], t[kk2 + 1][nn]);
        *(__half2*)&dst[(size_t)(n0 + nn) * DIN + k0 + kk2] = p;
    }
}

// ---------------------------------------------------------------------------
// GEMM 1 (HMMA, cp.async 2-stage): QKV projection from g_Xh.
// z=0 -> Q(*QSCALE) [h][s][d]; z=1 -> K [h][s][d]; z=2 -> V^T [h][d][s].
// ---------------------------------------------------------------------------
__global__ __launch_bounds__(256) void qkv_hmma_kernel()
{
    extern __shared__ __align__(16) __half dsm[];
    const uint32_t base_u = smem_u32(dsm);

    const int tid = threadIdx.x;
    const int w   = tid >> 5;
    const int l   = tid & 31;
    const int g   = l >> 2;
    const int tg  = l & 3;
    const int wm  = (w >> 1) * 32;
    const int wn  = (w & 1) * 64;
    const int m0  = blockIdx.y * 128;
    const int n0  = blockIdx.x * 128;
    const int z   = blockIdx.z;

    const __half* Wt = g_Wqkvt + (size_t)z * DIN * DIN;

    auto stage = [&](int k0, int buf) {
        uint32_t xu = base_u + (uint32_t)buf * 18432u;
        uint32_t wu = base_u + 36864u + (uint32_t)buf * 18432u;
        #pragma unroll
        for (int i = 0; i < 4; i++) {
            int ch  = tid + i * 256;
            int row = ch >> 3;
            int c   = (ch & 7) * 8;
            cp16(xu + row * 144 + c * 2, g_Xh + (size_t)(m0 + row) * DIN + k0 + c);
            cp16(wu + row * 144 + c * 2, Wt   + (size_t)(n0 + row) * DIN + k0 + c);
        }
        CP_COMMIT();
    };

    float acc[2][8][4];
    #pragma unroll
    for (int mf = 0; mf < 2; mf++)
        #pragma unroll
        for (int j = 0; j < 8; j++)
            #pragma unroll
            for (int r = 0; r < 4; r++) acc[mf][j][r] = 0.0f;

    stage(0, 0);
    CP_WAIT0();
    __syncthreads();

    for (int kq = 0; kq < 8; kq++) {
        const int buf = kq & 1;
        if (kq + 1 < 8) stage((kq + 1) * 64, buf ^ 1);

        const __half* sX = dsm + (size_t)buf * 9216;
        const __half* sW = dsm + 18432 + (size_t)buf * 9216;

        #pragma unroll
        for (int ks = 0; ks < 4; ks++) {
            int d0 = 16 * ks;
            uint32_t a[2][4];
            #pragma unroll
            for (int mf = 0; mf < 2; mf++) {
                int rb = wm + 16 * mf + g;
                a[mf][0] = *(const uint32_t*)&sX[(rb    ) * 72 + d0 + 2 * tg    ];
                a[mf][1] = *(const uint32_t*)&sX[(rb + 8) * 72 + d0 + 2 * tg    ];
                a[mf][2] = *(const uint32_t*)&sX[(rb    ) * 72 + d0 + 2 * tg + 8];
                a[mf][3] = *(const uint32_t*)&sX[(rb + 8) * 72 + d0 + 2 * tg + 8];
            }
            #pragma unroll
            for (int j = 0; j < 8; j++) {
                uint32_t b0 = *(const uint32_t*)&sW[(wn + 8 * j + g) * 72 + d0 + 2 * tg    ];
                uint32_t b1 = *(const uint32_t*)&sW[(wn + 8 * j + g) * 72 + d0 + 2 * tg + 8];
                mma16816(acc[0][j], a[0][0], a[0][1], a[0][2], a[0][3], b0, b1);
                mma16816(acc[1][j], a[1][0], a[1][1], a[1][2], a[1][3], b0, b1);
            }
        }

        if (kq + 1 < 8) { CP_WAIT0(); __syncthreads(); }
    }

    if (z == 2) {
        // V^T epilogue: pair adjacent rows via shfl_xor(4), store half2 along s.
        #pragma unroll
        for (int mf = 0; mf < 2; mf++) {
            int rbase = m0 + wm + 16 * mf;
            #pragma unroll
            for (int j = 0; j < 8; j++) {
                float p0 = __shfl_xor_sync(0xffffffffu, acc[mf][j][0], 4);
                float p1 = __shfl_xor_sync(0xffffffffu, acc[mf][j][1], 4);
                float p2 = __shfl_xor_sync(0xffffffffu, acc[mf][j][2], 4);
                float p3 = __shfl_xor_sync(0xffffffffu, acc[mf][j][3], 4);
                int col = n0 + wn + 8 * j + 2 * tg;
                int h = col >> 6, d = col & 63;
                __half* vt = g_Vth + (size_t)h * DHEAD * SEQ;
                if ((g & 1) == 0) {
                    int row = rbase + g;
                    *(__half2*)&vt[(size_t)(d    ) * SEQ + row] = __floats2half2_rn(acc[mf][j][0], p0);
                    *(__half2*)&vt[(size_t)(d + 1) * SEQ + row] = __floats2half2_rn(acc[mf][j][1], p1);
                } else {
                    int row = rbase + 8 + (g - 1);
                    *(__half2*)&vt[(size_t)(d    ) * SEQ + row] = __floats2half2_rn(p2, acc[mf][j][2]);
                    *(__half2*)&vt[(size_t)(d + 1) * SEQ + row] = __floats2half2_rn(p3, acc[mf][j][3]);
                }
            }
        }
    } else {
        const float sc = (z == 0) ? QSCALE : 1.0f;
        __half* Out = (z == 0) ? g_Qh : g_Kh;
        #pragma unroll
        for (int mf = 0; mf < 2; mf++) {
            int row = m0 + wm + 16 * mf + g;
            #pragma unroll
            for (int j = 0; j < 8; j++) {
                int col = n0 + wn + 8 * j + 2 * tg;
                int h = col >> 6, d = col & 63;
                __half2 lo = __floats2half2_rn(acc[mf][j][0] * sc, acc[mf][j][1] * sc);
                __half2 hi = __floats2half2_rn(acc[mf][j][2] * sc, acc[mf][j][3] * sc);
                *(__half2*)&Out[((size_t)h * SEQ + row    ) * DHEAD + d] = lo;
                *(__half2*)&Out[((size_t)h * SEQ + row + 8) * DHEAD + d] = hi;
            }
        }
    }
}

// ---------------------------------------------------------------------------
// Flash attention: R14 pipeline (4-buffer ring, stage 2 ahead, wait_group 1,
// sync every 2nd tile), but 4 warps x 32 rows: each B-fragment ldsm now feeds
// 4 MMAs (2 m-frags), halving the cross-warp-redundant LDS traffic that was
// the measured co-limiter (L1 53%).
// 128 threads = 4 warps: wm = w&1 (rows 32*wm..+31), wn = w>>1 (32-key half).
// smem bytes: sQ 0..9216 | K bufs 9216+i*9216 (i<4) | V bufs 46080+i*9216.
// Total 82944 B; 2 CTAs/SM. Reduction scratch reuses K bufs 0-1
// (64 slots x 72 floats, 288 B stride = 18432 B).
// ---------------------------------------------------------------------------
__global__ __launch_bounds__(128, 2) void attn_mma_kernel()
{
    extern __shared__ __align__(16) __half dynsm[];
    const uint32_t base_u = smem_u32(dynsm);

    const int tid = threadIdx.x;
    const int w   = tid >> 5;
    const int l   = tid & 31;
    const int g   = l >> 2;
    const int tg  = l & 3;
    const int wm  = w & 1;      // m row-group: rows 32*wm..32*wm+31
    const int wn  = w >> 1;     // key half: keys 32*wn..32*wn+31
    const int h   = blockIdx.y;
    const uint32_t ONE2 = 0x3C003C00u;

    // ldmatrix lane-constant byte offsets (row pitch 72 halves = 144 B)
    const int l7 = l & 7, t4 = l >> 3;
    const uint32_t koff = ((((t4 >> 1) * 8 + l7) * 72) + (t4 & 1) * 8) * 2;
    const uint32_t qoff = ((((t4 & 1) * 8 + l7) * 72) + (t4 >> 1) * 8) * 2;

    float* scratch = (float*)(dynsm + 4608);   // byte 9216 = K bufs 0-1 region

    auto stageKV = [&](int kt2, int buf) {
        uint32_t ku = base_u + 9216u  + (uint32_t)buf * 9216u;
        uint32_t vu = base_u + 46080u + (uint32_t)buf * 9216u;
        const __half* Kg = g_Kh  + ((size_t)h * SEQ + kt2 * 64) * DHEAD;
        const __half* Vg = g_Vth + (size_t)h * DHEAD * SEQ + kt2 * 64;
        #pragma unroll
        for (int i = 0; i < 4; i++) {
            int ch  = tid + i * 128;          // 0..511
            int row = ch >> 3;
            int c   = (ch & 7) * 8;
            cp16(ku + row * 144 + c * 2, Kg + row * DHEAD + c);
            cp16(vu + row * 144 + c * 2, Vg + (size_t)row * SEQ + c);
        }
        CP_COMMIT();
    };

    for (int pass = 0; pass < 2; pass++) {
        const int qt = (pass == 0) ? (int)blockIdx.x : 63 - (int)blockIdx.x;
        const int m0 = qt * 64;
        const int nkt = qt + 1;

        __syncthreads();   // previous pass fully consumed (bufs, sQ, scratch)

        // Stage Q + KV(0) as one group; KV(1) as a second group if present
        {
            const __half* Qg = g_Qh + ((size_t)h * SEQ + m0) * DHEAD;
            #pragma unroll
            for (int i = 0; i < 4; i++) {
                int ch  = tid + i * 128;
                int row = ch >> 3;
                int c   = (ch & 7) * 8;
                cp16(base_u + row * 144 + c * 2, Qg + row * DHEAD + c);
            }
        }
        stageKV(0, 0);                       // commits {Q, KV0}
        if (nkt > 1) { stageKV(1, 1); CP_WAIT1(); }
        else         { CP_WAIT0(); }
        __syncthreads();

        // Q fragments: 2 m-frags (16-row groups 2*wm and 2*wm+1)
        uint32_t qf[2][4][4];
        #pragma unroll
        for (int mf = 0; mf < 2; mf++)
            #pragma unroll
            for (int ks = 0; ks < 4; ks++)
                ldsm_x4(base_u + (1152 * (2 * wm + mf) + 16 * ks) * 2 + qoff,
                        qf[mf][ks][0], qf[mf][ks][1], qf[mf][ks][2], qf[mf][ks][3]);

        float o[2][8][4];
        #pragma unroll
        for (int mf = 0; mf < 2; mf++)
            #pragma unroll
            for (int j = 0; j < 8; j++)
                #pragma unroll
                for (int r = 0; r < 4; r++) o[mf][j][r] = 0.0f;
        float lsf[2][4] = {{0.f,0.f,0.f,0.f},{0.f,0.f,0.f,0.f}};

        const int rowA0 = m0 + 32 * wm + g;        // mf=0 rows: rowA0, rowA0+8
        const int rowA1 = rowA0 + 16;              // mf=1 rows

        for (int kt = 0; kt < nkt; kt++) {
            if (kt + 2 < nkt) stageKV(kt + 2, (kt + 2) & 3);

            const uint32_t sK_u = base_u + 9216u  + (uint32_t)(kt & 3) * 9216u;
            const uint32_t sV_u = base_u + 46080u + (uint32_t)(kt & 3) * 9216u;

            // S = Q K^T (log2-domain), fp16 accum; each B-ldsm feeds 4 MMAs
            uint32_t plo[2][4], phi[2][4];
            #pragma unroll
            for (int mf = 0; mf < 2; mf++)
                #pragma unroll
                for (int j = 0; j < 4; j++) { plo[mf][j] = 0u; phi[mf][j] = 0u; }

            #pragma unroll
            for (int ks = 0; ks < 4; ks++) {
                #pragma unroll
                for (int jp = 0; jp < 2; jp++) {
                    uint32_t b0, b1, b2, b3;
                    ldsm_x4(sK_u + (1152 * (2 * wn + jp) + 16 * ks) * 2 + koff,
                            b0, b1, b2, b3);
                    #pragma unroll
                    for (int mf = 0; mf < 2; mf++) {
                        mma16816_f16(plo[mf][2 * jp    ], phi[mf][2 * jp    ],
                                     qf[mf][ks][0], qf[mf][ks][1], qf[mf][ks][2], qf[mf][ks][3],
                                     b0, b1);
                        mma16816_f16(plo[mf][2 * jp + 1], phi[mf][2 * jp + 1],
                                     qf[mf][ks][0], qf[mf][ks][1], qf[mf][ks][2], qf[mf][ks][3],
                                     b2, b3);
                    }
                }
            }

            // P = 2^S directly on the fp16 accumulator regs
            #pragma unroll
            for (int mf = 0; mf < 2; mf++)
                #pragma unroll
                for (int j = 0; j < 4; j++) {
                    asm("ex2.approx.f16x2 %0, %0;" : "+r"(plo[mf][j]));
                    asm("ex2.approx.f16x2 %0, %0;" : "+r"(phi[mf][j]));
                }

            // Causal mask (diag tile only): zero exp'd halves past the diagonal
            if (kt == qt) {
                const int kb = kt * 64 + 32 * wn;
                #pragma unroll
                for (int mf = 0; mf < 2; mf++) {
                    const int r0 = (mf == 0) ? rowA0 : rowA1;
                    #pragma unroll
                    for (int j = 0; j < 4; j++) {
                        int col = kb + 8 * j + 2 * tg;
                        uint32_t m0b = (col <= r0     ? 0x0000FFFFu : 0u)
                                     | (col <  r0     ? 0xFFFF0000u : 0u);
                        uint32_t m1b = (col <= r0 + 8 ? 0x0000FFFFu : 0u)
                                     | (col <  r0 + 8 ? 0xFFFF0000u : 0u);
                        plo[mf][j] &= m0b;
                        phi[mf][j] &= m1b;
                    }
                }
            }

            // O += P V; each V-ldsm feeds 4 MMAs. Row sums via ones-MMA (fp32)
            #pragma unroll
            for (int kk = 0; kk < 2; kk++) {
                #pragma unroll
                for (int mf = 0; mf < 2; mf++)
                    mma16816(lsf[mf], plo[mf][2 * kk], phi[mf][2 * kk],
                             plo[mf][2 * kk + 1], phi[mf][2 * kk + 1], ONE2, ONE2);
                const int kkg = 2 * wn + kk;
                #pragma unroll
                for (int jp = 0; jp < 4; jp++) {
                    uint32_t b0, b1, b2, b3;
                    ldsm_x4(sV_u + (1152 * jp + 16 * kkg) * 2 + koff, b0, b1, b2, b3);
                    #pragma unroll
                    for (int mf = 0; mf < 2; mf++) {
                        mma16816(o[mf][2 * jp    ],
                                 plo[mf][2 * kk], phi[mf][2 * kk],
                                 plo[mf][2 * kk + 1], phi[mf][2 * kk + 1], b0, b1);
                        mma16816(o[mf][2 * jp + 1],
                                 plo[mf][2 * kk], phi[mf][2 * kk],
                                 plo[mf][2 * kk + 1], phi[mf][2 * kk + 1], b2, b3);
                    }
                }
            }

            if (kt + 1 < nkt) {
                if (kt + 2 < nkt) CP_WAIT1();   // t+1 landed; t+2 may fly
                else              CP_WAIT0();
                if (kt & 1) __syncthreads();    // barrier every 2nd tile
            }
        }

        // Cross-warp (wn pair) reduction via smem scratch, then write.
        __syncthreads();   // all MMA consumers done; K bufs now reusable
        if (wn == 1) {
            float* dst = scratch + (size_t)(wm * 32 + l) * 72;   // 288 B stride
            #pragma unroll
            for (int mf = 0; mf < 2; mf++)
                #pragma unroll
                for (int j = 0; j < 8; j++)
                    *(float4*)(dst + mf * 32 + 4 * j) =
                        make_float4(o[mf][j][0], o[mf][j][1], o[mf][j][2], o[mf][j][3]);
            dst[64] = lsf[0][0];
            dst[65] = lsf[0][2];
            dst[66] = lsf[1][0];
            dst[67] = lsf[1][2];
        }
        __syncthreads();
        if (wn == 0) {
            const float* src = scratch + (size_t)(wm * 32 + l) * 72;
            #pragma unroll
            for (int mf = 0; mf < 2; mf++)
                #pragma unroll
                for (int j = 0; j < 8; j++) {
                    float4 v = *(const float4*)(src + mf * 32 + 4 * j);
                    o[mf][j][0] += v.x; o[mf][j][1] += v.y;
                    o[mf][j][2] += v.z; o[mf][j][3] += v.w;
                }

            #pragma unroll
            for (int mf = 0; mf < 2; mf++) {
                const int r0 = (mf == 0) ? rowA0 : rowA1;
                const float inv0 = 1.0f / (lsf[mf][0] + src[64 + 2 * mf]);
                const float inv1 = 1.0f / (lsf[mf][2] + src[65 + 2 * mf]);

                __half* dst0 = g_Ah + (size_t)(r0    ) * DIN + h * DHEAD;
                __half* dst1 = g_Ah + (size_t)(r0 + 8) * DIN + h * DHEAD;
                #pragma unroll
                for (int jd = 0; jd < 8; jd++) {
                    int d = 8 * jd + 2 * tg;
                    __half2 a = __floats2half2_rn(o[mf][jd][0] * inv0, o[mf][jd][1] * inv0);
                    __half2 b = __floats2half2_rn(o[mf][jd][2] * inv1, o[mf][jd][3] * inv1);
                    *(__half2*)(dst0 + d) = a;
                    *(__half2*)(dst1 + d) = b;
                }
            }
        }
    }
}

// ---------------------------------------------------------------------------
// GEMM 2 (HMMA, cp.async 2-stage): out = g_Ah @ Wo.
// ---------------------------------------------------------------------------
__global__ __launch_bounds__(256) void out_hmma_kernel(float* __restrict__ out)
{
    extern __shared__ __align__(16) __half dsm[];
    const uint32_t base_u = smem_u32(dsm);

    const int tid = threadIdx.x;
    const int w   = tid >> 5;
    const int l   = tid & 31;
    const int g   = l >> 2;
    const int tg  = l & 3;
    const int wm  = (w >> 1) * 32;
    const int wn  = (w & 1) * 64;
    const int m0  = blockIdx.y * 128;
    const int n0  = blockIdx.x * 128;

    auto stage = [&](int k0, int buf) {
        uint32_t au = base_u + (uint32_t)buf * 18432u;
        uint32_t wu = base_u + 36864u + (uint32_t)buf * 18432u;
        #pragma unroll
        for (int i = 0; i < 4; i++) {
            int ch  = tid + i * 256;
            int row = ch >> 3;
            int c   = (ch & 7) * 8;
            cp16(au + row * 144 + c * 2, g_Ah  + (size_t)(m0 + row) * DIN + k0 + c);
            cp16(wu + row * 144 + c * 2, g_Wot + (size_t)(n0 + row) * DIN + k0 + c);
        }
        CP_COMMIT();
    };

    float acc[2][8][4];
    #pragma unroll
    for (int mf = 0; mf < 2; mf++)
        #pragma unroll
        for (int j = 0; j < 8; j++)
            #pragma unroll
            for (int r = 0; r < 4; r++) acc[mf][j][r] = 0.0f;

    stage(0, 0);
    CP_WAIT0();
    __syncthreads();

    for (int kq = 0; kq < 8; kq++) {
        const int buf = kq & 1;
        if (kq + 1 < 8) stage((kq + 1) * 64, buf ^ 1);

        const __half* sA = dsm + (size_t)buf * 9216;
        const __half* sW = dsm + 18432 + (size_t)buf * 9216;

        #pragma unroll
        for (int ks = 0; ks < 4; ks++) {
            int d0 = 16 * ks;
            uint32_t a[2][4];
            #pragma unroll
            for (int mf = 0; mf < 2; mf++) {
                int rb = wm + 16 * mf + g;
                a[mf][0] = *(const uint32_t*)&sA[(rb    ) * 72 + d0 + 2 * tg    ];
                a[mf][1] = *(const uint32_t*)&sA[(rb + 8) * 72 + d0 + 2 * tg    ];
                a[mf][2] = *(const uint32_t*)&sA[(rb    ) * 72 + d0 + 2 * tg + 8];
                a[mf][3] = *(const uint32_t*)&sA[(rb + 8) * 72 + d0 + 2 * tg + 8];
            }
            #pragma unroll
            for (int j = 0; j < 8; j++) {
                uint32_t b0 = *(const uint32_t*)&sW[(wn + 8 * j + g) * 72 + d0 + 2 * tg    ];
                uint32_t b1 = *(const uint32_t*)&sW[(wn + 8 * j + g) * 72 + d0 + 2 * tg + 8];
                mma16816(acc[0][j], a[0][0], a[0][1], a[0][2], a[0][3], b0, b1);
                mma16816(acc[1][j], a[1][0], a[1][1], a[1][2], a[1][3], b0, b1);
            }
        }

        if (kq + 1 < 8) { CP_WAIT0(); __syncthreads(); }
    }

    #pragma unroll
    for (int mf = 0; mf < 2; mf++) {
        int row = m0 + wm + 16 * mf + g;
        #pragma unroll
        for (int j = 0; j < 8; j++) {
            int col = n0 + wn + 8 * j + 2 * tg;
            *(float2*)&out[(size_t)(row    ) * DIN + col] = make_float2(acc[mf][j][0], acc[mf][j][1]);
            *(float2*)&out[(size_t)(row + 8) * DIN + col] = make_float2(acc[mf][j][2], acc[mf][j][3]);
        }
    }
}

// ---------------------------------------------------------------------------
// Launch
// ---------------------------------------------------------------------------
extern "C" void kernel_launch(void* const* d_in, const int* in_sizes, int n_in,
                              void* d_out, int out_size)
{
    (void)in_sizes; (void)n_in; (void)out_size;
    const float* x  = (const float*)d_in[0];
    const float* Wq = (const float*)d_in[1];
    const float* Wk = (const float*)d_in[2];
    const float* Wv = (const float*)d_in[3];
    const float* Wo = (const float*)d_in[4];
    float* out = (float*)d_out;

    const int gemm_smem = 73728;   // 2 x (128x72 + 128x72) halves
    const int attn_smem = 82944;   // sQ + 4x sK + 4x sVt
    cudaFuncSetAttribute(qkv_hmma_kernel,
                         cudaFuncAttributeMaxDynamicSharedMemorySize, gemm_smem);
    cudaFuncSetAttribute(out_hmma_kernel,
                         cudaFuncAttributeMaxDynamicSharedMemorySize, gemm_smem);
    cudaFuncSetAttribute(attn_mma_kernel,
                         cudaFuncAttributeMaxDynamicSharedMemorySize, attn_smem);

    xcast_kernel<<<SEQ * DIN / 1024, 256>>>(x);
    wtrans_kernel<<<dim3(8, 8, 4), 256>>>(Wq, Wk, Wv, Wo);
    qkv_hmma_kernel<<<dim3(4, 32, 3), 256, gemm_smem>>>();
    attn_mma_kernel<<<dim3(32, HEADS), 128, attn_smem>>>();
    out_hmma_kernel<<<dim3(4, 32), 256, gemm_smem>>>(out);
}

// round 17
// speedup vs baseline: 1.0358x; 1.0358x over previous
#include <cuda_runtime.h>
#include <cuda_fp16.h>
#include <cstdint>

#define SEQ   4096
#define DIN   512
#define HEADS 8
#define DHEAD 64

// Q pre-scale: (1/sqrt(64)) * log2(e)  ->  P = exp2(S)
#define QSCALE 0.1803368801111204f

// ---------------------------------------------------------------------------
// Scratch (__device__ globals; no allocation allowed)
// ---------------------------------------------------------------------------
__device__ __half g_Xh   [SEQ * DIN];             // x cast to fp16
__device__ __half g_Qh   [HEADS * SEQ * DHEAD];   // [h][s][d], pre-scaled by QSCALE
__device__ __half g_Kh   [HEADS * SEQ * DHEAD];   // [h][s][d]
__device__ __half g_Vth  [HEADS * DHEAD * SEQ];   // [h][d][s] transposed
__device__ __half g_Ah   [SEQ * DIN];             // attn out fp16, [s][h*64+v]
__device__ __half g_Wqkvt[3 * DIN * DIN];         // [z][n][k] transposed weights
__device__ __half g_Wot  [DIN * DIN];             // [n][k] transposed Wo

// m16n8k16 HMMA, fp32 accum
__device__ __forceinline__ void mma16816(float c[4],
                                         uint32_t a0, uint32_t a1, uint32_t a2, uint32_t a3,
                                         uint32_t b0, uint32_t b1)
{
    asm volatile(
        "mma.sync.aligned.m16n8k16.row.col.f32.f16.f16.f32 "
        "{%0,%1,%2,%3}, {%4,%5,%6,%7}, {%8,%9}, {%0,%1,%2,%3};"
        : "+f"(c[0]), "+f"(c[1]), "+f"(c[2]), "+f"(c[3])
        : "r"(a0), "r"(a1), "r"(a2), "r"(a3), "r"(b0), "r"(b1));
}

// m16n8k16 HMMA, fp16 accum; C = {c0: row g, c1: row g+8}
__device__ __forceinline__ void mma16816_f16(uint32_t& c0, uint32_t& c1,
                                             uint32_t a0, uint32_t a1, uint32_t a2, uint32_t a3,
                                             uint32_t b0, uint32_t b1)
{
    asm volatile(
        "mma.sync.aligned.m16n8k16.row.col.f16.f16.f16.f16 "
        "{%0,%1}, {%2,%3,%4,%5}, {%6,%7}, {%0,%1};"
        : "+r"(c0), "+r"(c1)
        : "r"(a0), "r"(a1), "r"(a2), "r"(a3), "r"(b0), "r"(b1));
}

__device__ __forceinline__ void ldsm_x4(uint32_t addr,
                                        uint32_t& r0, uint32_t& r1,
                                        uint32_t& r2, uint32_t& r3)
{
    asm volatile("ldmatrix.sync.aligned.m8n8.x4.shared.b16 {%0,%1,%2,%3}, [%4];"
                 : "=r"(r0), "=r"(r1), "=r"(r2), "=r"(r3) : "r"(addr));
}

__device__ __forceinline__ uint32_t smem_u32(const void* p) {
    uint32_t a;
    asm("{ .reg .u64 t; cvta.to.shared.u64 t, %1; cvt.u32.u64 %0, t; }"
        : "=r"(a) : "l"(p));
    return a;
}
__device__ __forceinline__ void cp16(uint32_t dst, const void* src) {
    asm volatile("cp.async.cg.shared.global [%0], [%1], 16;"
                 :: "r"(dst), "l"(src) : "memory");
}
#define CP_COMMIT() asm volatile("cp.async.commit_group;" ::: "memory")
#define CP_WAIT0()  asm volatile("cp.async.wait_group 0;" ::: "memory")
#define CP_WAIT1()  asm volatile("cp.async.wait_group 1;" ::: "memory")

// ---------------------------------------------------------------------------
// x -> fp16 cast
// ---------------------------------------------------------------------------
__global__ __launch_bounds__(256) void xcast_kernel(const float* __restrict__ x)
{
    int idx = (blockIdx.x * 256 + threadIdx.x) * 4;
    float4 v = *(const float4*)(x + idx);
    __half2 h0 = __floats2half2_rn(v.x, v.y);
    __half2 h1 = __floats2half2_rn(v.z, v.w);
    uint2 u; u.x = *(uint32_t*)&h0; u.y = *(uint32_t*)&h1;
    *(uint2*)&g_Xh[idx] = u;
}

// ---------------------------------------------------------------------------
// Prep: cast+transpose weights. z=0/1/2 -> Wq/Wk/Wv -> g_Wqkvt[z][n][k];
// z=3 -> Wo -> g_Wot[n][k].
// ---------------------------------------------------------------------------
__global__ __launch_bounds__(256) void wtrans_kernel(
    const float* __restrict__ Wq, const float* __restrict__ Wk,
    const float* __restrict__ Wv, const float* __restrict__ Wo)
{
    __shared__ float t[64][65];
    const int tid = threadIdx.x;
    const int k0  = blockIdx.x * 64;
    const int n0  = blockIdx.y * 64;
    const int z   = blockIdx.z;
    const float* W = (z == 0) ? Wq : (z == 1) ? Wk : (z == 2) ? Wv : Wo;

    #pragma unroll
    for (int i = 0; i < 16; i++) {
        int idx = tid + i * 256;
        int kk = idx >> 6, nn = idx & 63;
        float v;
        if (z < 3) v = W[(size_t)(n0 >> 6) * (DIN * DHEAD) + (size_t)(k0 + kk) * DHEAD + nn];
        else       v = W[(size_t)(k0 + kk) * DIN + n0 + nn];
        t[kk][nn] = v;
    }
    __syncthreads();

    __half* dst = (z < 3) ? (g_Wqkvt + (size_t)z * DIN * DIN) : g_Wot;
    #pragma unroll
    for (int i = 0; i < 8; i++) {
        int idx = tid + i * 256;
        int nn  = idx >> 5;
        int kk2 = (idx & 31) * 2;
        __half2 p = __floats2half2_rn(t[kk2][nn], t[kk2 + 1][nn]);
        *(__half2*)&dst[(size_t)(n0 + nn) * DIN + k0 + kk2] = p;
    }
}

// ---------------------------------------------------------------------------
// GEMM 1 (HMMA, cp.async 2-stage, ldsm fragments): QKV projection from g_Xh.
// z=0 -> Q(*QSCALE) [h][s][d]; z=1 -> K [h][s][d]; z=2 -> V^T [h][d][s].
// A(x) uses the attention Q-fragment ldsm pattern; B(W^T) the K pattern.
// ---------------------------------------------------------------------------
__global__ __launch_bounds__(256) void qkv_hmma_kernel()
{
    extern __shared__ __align__(16) __half dsm[];
    const uint32_t base_u = smem_u32(dsm);

    const int tid = threadIdx.x;
    const int w   = tid >> 5;
    const int l   = tid & 31;
    const int g   = l >> 2;
    const int tg  = l & 3;
    const int wm  = (w >> 1) * 32;
    const int wn  = (w & 1) * 64;
    const int m0  = blockIdx.y * 128;
    const int n0  = blockIdx.x * 128;
    const int z   = blockIdx.z;

    const int mrow16 = (w >> 1) * 2;      // first 16-row m-frag index
    const int jpbase = (w & 1) * 4;       // first 16-col n-group index

    // ldmatrix lane-constant byte offsets (row pitch 72 halves = 144 B)
    const int l7 = l & 7, t4 = l >> 3;
    const uint32_t koff = ((((t4 >> 1) * 8 + l7) * 72) + (t4 & 1) * 8) * 2;
    const uint32_t qoff = ((((t4 & 1) * 8 + l7) * 72) + (t4 >> 1) * 8) * 2;

    const __half* Wt = g_Wqkvt + (size_t)z * DIN * DIN;

    auto stage = [&](int k0, int buf) {
        uint32_t xu = base_u + (uint32_t)buf * 18432u;
        uint32_t wu = base_u + 36864u + (uint32_t)buf * 18432u;
        #pragma unroll
        for (int i = 0; i < 4; i++) {
            int ch  = tid + i * 256;
            int row = ch >> 3;
            int c   = (ch & 7) * 8;
            cp16(xu + row * 144 + c * 2, g_Xh + (size_t)(m0 + row) * DIN + k0 + c);
            cp16(wu + row * 144 + c * 2, Wt   + (size_t)(n0 + row) * DIN + k0 + c);
        }
        CP_COMMIT();
    };

    float acc[2][8][4];
    #pragma unroll
    for (int mf = 0; mf < 2; mf++)
        #pragma unroll
        for (int j = 0; j < 8; j++)
            #pragma unroll
            for (int r = 0; r < 4; r++) acc[mf][j][r] = 0.0f;

    stage(0, 0);
    CP_WAIT0();
    __syncthreads();

    for (int kq = 0; kq < 8; kq++) {
        const int buf = kq & 1;
        if (kq + 1 < 8) stage((kq + 1) * 64, buf ^ 1);

        const uint32_t sX_u = base_u + (uint32_t)buf * 18432u;
        const uint32_t sW_u = base_u + 36864u + (uint32_t)buf * 18432u;

        #pragma unroll
        for (int ks = 0; ks < 4; ks++) {
            uint32_t a[2][4];
            #pragma unroll
            for (int mf = 0; mf < 2; mf++)
                ldsm_x4(sX_u + (1152 * (mrow16 + mf) + 16 * ks) * 2 + qoff,
                        a[mf][0], a[mf][1], a[mf][2], a[mf][3]);
            #pragma unroll
            for (int jp = 0; jp < 4; jp++) {
                uint32_t b0, b1, b2, b3;
                ldsm_x4(sW_u + (1152 * (jpbase + jp) + 16 * ks) * 2 + koff,
                        b0, b1, b2, b3);
                mma16816(acc[0][2 * jp    ], a[0][0], a[0][1], a[0][2], a[0][3], b0, b1);
                mma16816(acc[0][2 * jp + 1], a[0][0], a[0][1], a[0][2], a[0][3], b2, b3);
                mma16816(acc[1][2 * jp    ], a[1][0], a[1][1], a[1][2], a[1][3], b0, b1);
                mma16816(acc[1][2 * jp + 1], a[1][0], a[1][1], a[1][2], a[1][3], b2, b3);
            }
        }

        if (kq + 1 < 8) { CP_WAIT0(); __syncthreads(); }
    }

    if (z == 2) {
        // V^T epilogue: pair adjacent rows via shfl_xor(4), store half2 along s.
        #pragma unroll
        for (int mf = 0; mf < 2; mf++) {
            int rbase = m0 + wm + 16 * mf;
            #pragma unroll
            for (int j = 0; j < 8; j++) {
                float p0 = __shfl_xor_sync(0xffffffffu, acc[mf][j][0], 4);
                float p1 = __shfl_xor_sync(0xffffffffu, acc[mf][j][1], 4);
                float p2 = __shfl_xor_sync(0xffffffffu, acc[mf][j][2], 4);
                float p3 = __shfl_xor_sync(0xffffffffu, acc[mf][j][3], 4);
                int col = n0 + wn + 8 * j + 2 * tg;
                int h = col >> 6, d = col & 63;
                __half* vt = g_Vth + (size_t)h * DHEAD * SEQ;
                if ((g & 1) == 0) {
                    int row = rbase + g;
                    *(__half2*)&vt[(size_t)(d    ) * SEQ + row] = __floats2half2_rn(acc[mf][j][0], p0);
                    *(__half2*)&vt[(size_t)(d + 1) * SEQ + row] = __floats2half2_rn(acc[mf][j][1], p1);
                } else {
                    int row = rbase + 8 + (g - 1);
                    *(__half2*)&vt[(size_t)(d    ) * SEQ + row] = __floats2half2_rn(p2, acc[mf][j][2]);
                    *(__half2*)&vt[(size_t)(d + 1) * SEQ + row] = __floats2half2_rn(p3, acc[mf][j][3]);
                }
            }
        }
    } else {
        const float sc = (z == 0) ? QSCALE : 1.0f;
        __half* Out = (z == 0) ? g_Qh : g_Kh;
        #pragma unroll
        for (int mf = 0; mf < 2; mf++) {
            int row = m0 + wm + 16 * mf + g;
            #pragma unroll
            for (int j = 0; j < 8; j++) {
                int col = n0 + wn + 8 * j + 2 * tg;
                int h = col >> 6, d = col & 63;
                __half2 lo = __floats2half2_rn(acc[mf][j][0] * sc, acc[mf][j][1] * sc);
                __half2 hi = __floats2half2_rn(acc[mf][j][2] * sc, acc[mf][j][3] * sc);
                *(__half2*)&Out[((size_t)h * SEQ + row    ) * DHEAD + d] = lo;
                *(__half2*)&Out[((size_t)h * SEQ + row + 8) * DHEAD + d] = hi;
            }
        }
    }
}

// ---------------------------------------------------------------------------
// Flash attention (R14, best measured): 4-buffer K/V ring, stage 2 ahead,
// wait_group 1, sync every 2nd tile. fp16 S-accumulators; ex2 on accum regs;
// AND-mask causal; ones-MMA row sums. 256 threads = 8 warps: wm = w&3
// (16-row group), wn = w>>2 (32-key half).
// smem bytes: sQ 0..9216 | K bufs 9216+i*9216 (i<4) | V bufs 46080+i*9216.
// Total 82944 B; 2 CTAs/SM. Reduction scratch reuses K bufs 0-1
// (128 slots x 36 floats, 144 B stride).
// ---------------------------------------------------------------------------
__global__ __launch_bounds__(256, 2) void attn_mma_kernel()
{
    extern __shared__ __align__(16) __half dynsm[];
    const uint32_t base_u = smem_u32(dynsm);

    const int tid = threadIdx.x;
    const int w   = tid >> 5;
    const int l   = tid & 31;
    const int g   = l >> 2;
    const int tg  = l & 3;
    const int wm  = w & 3;      // m row-group: rows 16*wm..16*wm+15
    const int wn  = w >> 2;     // key half: keys 32*wn..32*wn+31
    const int h   = blockIdx.y;
    const uint32_t ONE2 = 0x3C003C00u;

    // ldmatrix lane-constant byte offsets (row pitch 72 halves = 144 B)
    const int l7 = l & 7, t4 = l >> 3;
    const uint32_t koff = ((((t4 >> 1) * 8 + l7) * 72) + (t4 & 1) * 8) * 2;
    const uint32_t qoff = ((((t4 & 1) * 8 + l7) * 72) + (t4 >> 1) * 8) * 2;

    float* scratch = (float*)(dynsm + 4608);   // byte 9216 = K bufs 0-1 region

    auto stageKV = [&](int kt2, int buf) {
        uint32_t ku = base_u + 9216u  + (uint32_t)buf * 9216u;
        uint32_t vu = base_u + 46080u + (uint32_t)buf * 9216u;
        const __half* Kg = g_Kh  + ((size_t)h * SEQ + kt2 * 64) * DHEAD;
        const __half* Vg = g_Vth + (size_t)h * DHEAD * SEQ + kt2 * 64;
        #pragma unroll
        for (int i = 0; i < 2; i++) {
            int ch  = tid + i * 256;          // 0..511
            int row = ch >> 3;
            int c   = (ch & 7) * 8;
            cp16(ku + row * 144 + c * 2, Kg + row * DHEAD + c);
            cp16(vu + row * 144 + c * 2, Vg + (size_t)row * SEQ + c);
        }
        CP_COMMIT();
    };

    for (int pass = 0; pass < 2; pass++) {
        const int qt = (pass == 0) ? (int)blockIdx.x : 63 - (int)blockIdx.x;
        const int m0 = qt * 64;
        const int nkt = qt + 1;

        __syncthreads();   // previous pass fully consumed (bufs, sQ, scratch)

        // Stage Q + KV(0) as one group; KV(1) as a second group if present
        {
            const __half* Qg = g_Qh + ((size_t)h * SEQ + m0) * DHEAD;
            #pragma unroll
            for (int i = 0; i < 2; i++) {
                int ch  = tid + i * 256;
                int row = ch >> 3;
                int c   = (ch & 7) * 8;
                cp16(base_u + row * 144 + c * 2, Qg + row * DHEAD + c);
            }
        }
        stageKV(0, 0);                       // commits {Q, KV0}
        if (nkt > 1) { stageKV(1, 1); CP_WAIT1(); }
        else         { CP_WAIT0(); }
        __syncthreads();

        // Q fragments (this warp's 16-row group)
        uint32_t qf[4][4];
        #pragma unroll
        for (int ks = 0; ks < 4; ks++)
            ldsm_x4(base_u + (1152 * wm + 16 * ks) * 2 + qoff,
                    qf[ks][0], qf[ks][1], qf[ks][2], qf[ks][3]);

        float o[8][4];
        #pragma unroll
        for (int j = 0; j < 8; j++)
            #pragma unroll
            for (int r = 0; r < 4; r++) o[j][r] = 0.0f;
        float lsf[4] = {0.f, 0.f, 0.f, 0.f};

        const int row0 = m0 + 16 * wm + g;

        for (int kt = 0; kt < nkt; kt++) {
            if (kt + 2 < nkt) stageKV(kt + 2, (kt + 2) & 3);

            const uint32_t sK_u = base_u + 9216u  + (uint32_t)(kt & 3) * 9216u;
            const uint32_t sV_u = base_u + 46080u + (uint32_t)(kt & 3) * 9216u;

            // S = Q K^T (log2-domain), fp16 accumulators
            uint32_t plo[4], phi[4];
            #pragma unroll
            for (int j = 0; j < 4; j++) { plo[j] = 0u; phi[j] = 0u; }

            #pragma unroll
            for (int ks = 0; ks < 4; ks++) {
                #pragma unroll
                for (int jp = 0; jp < 2; jp++) {
                    uint32_t b0, b1, b2, b3;
                    ldsm_x4(sK_u + (1152 * (2 * wn + jp) + 16 * ks) * 2 + koff,
                            b0, b1, b2, b3);
                    mma16816_f16(plo[2 * jp    ], phi[2 * jp    ],
                                 qf[ks][0], qf[ks][1], qf[ks][2], qf[ks][3], b0, b1);
                    mma16816_f16(plo[2 * jp + 1], phi[2 * jp + 1],
                                 qf[ks][0], qf[ks][1], qf[ks][2], qf[ks][3], b2, b3);
                }
            }

            // P = 2^S directly on the fp16 accumulator regs
            #pragma unroll
            for (int j = 0; j < 4; j++) {
                asm("ex2.approx.f16x2 %0, %0;" : "+r"(plo[j]));
                asm("ex2.approx.f16x2 %0, %0;" : "+r"(phi[j]));
            }

            // Causal mask (diag tile only): zero exp'd halves past the diagonal
            if (kt == qt) {
                const int kb = kt * 64 + 32 * wn;
                #pragma unroll
                for (int j = 0; j < 4; j++) {
                    int col = kb + 8 * j + 2 * tg;
                    uint32_t m0b = (col <= row0     ? 0x0000FFFFu : 0u)
                                 | (col <  row0     ? 0xFFFF0000u : 0u);
                    uint32_t m1b = (col <= row0 + 8 ? 0x0000FFFFu : 0u)
                                 | (col <  row0 + 8 ? 0xFFFF0000u : 0u);
                    plo[j] &= m0b;
                    phi[j] &= m1b;
                }
            }

            // O += P V over this warp's key half; row sums via ones-MMA (fp32)
            #pragma unroll
            for (int kk = 0; kk < 2; kk++) {
                uint32_t pa0 = plo[2 * kk],     pa1 = phi[2 * kk];
                uint32_t pa2 = plo[2 * kk + 1], pa3 = phi[2 * kk + 1];
                mma16816(lsf, pa0, pa1, pa2, pa3, ONE2, ONE2);
                const int kkg = 2 * wn + kk;
                #pragma unroll
                for (int jp = 0; jp < 4; jp++) {
                    uint32_t b0, b1, b2, b3;
                    ldsm_x4(sV_u + (1152 * jp + 16 * kkg) * 2 + koff, b0, b1, b2, b3);
                    mma16816(o[2 * jp    ], pa0, pa1, pa2, pa3, b0, b1);
                    mma16816(o[2 * jp + 1], pa0, pa1, pa2, pa3, b2, b3);
                }
            }

            if (kt + 1 < nkt) {
                if (kt + 2 < nkt) CP_WAIT1();   // t+1 landed; t+2 may fly
                else              CP_WAIT0();
                if (kt & 1) __syncthreads();    // barrier every 2nd tile
            }
        }

        // Cross-warp (wn pair) reduction via smem scratch, then write.
        __syncthreads();   // all MMA consumers done; K bufs now reusable
        if (wn == 1) {
            float* dst = scratch + (size_t)(wm * 32 + l) * 36;   // 144 B stride
            #pragma unroll
            for (int j = 0; j < 8; j++) {
                *(float4*)(dst + 4 * j) = make_float4(o[j][0], o[j][1], o[j][2], o[j][3]);
            }
            dst[32] = lsf[0];
            dst[33] = lsf[2];
        }
        __syncthreads();
        if (wn == 0) {
            const float* src = scratch + (size_t)(wm * 32 + l) * 36;
            #pragma unroll
            for (int j = 0; j < 8; j++) {
                float4 v = *(const float4*)(src + 4 * j);
                o[j][0] += v.x; o[j][1] += v.y; o[j][2] += v.z; o[j][3] += v.w;
            }
            const float inv0 = 1.0f / (lsf[0] + src[32]);
            const float inv1 = 1.0f / (lsf[2] + src[33]);

            __half* dst0 = g_Ah + (size_t)(row0    ) * DIN + h * DHEAD;
            __half* dst1 = g_Ah + (size_t)(row0 + 8) * DIN + h * DHEAD;
            #pragma unroll
            for (int jd = 0; jd < 8; jd++) {
                int d = 8 * jd + 2 * tg;
                __half2 a = __floats2half2_rn(o[jd][0] * inv0, o[jd][1] * inv0);
                __half2 b = __floats2half2_rn(o[jd][2] * inv1, o[jd][3] * inv1);
                *(__half2*)(dst0 + d) = a;
                *(__half2*)(dst1 + d) = b;
            }
        }
    }
}

// ---------------------------------------------------------------------------
// GEMM 2 (HMMA, cp.async 2-stage, ldsm fragments): out = g_Ah @ Wo.
// ---------------------------------------------------------------------------
__global__ __launch_bounds__(256) void out_hmma_kernel(float* __restrict__ out)
{
    extern __shared__ __align__(16) __half dsm[];
    const uint32_t base_u = smem_u32(dsm);

    const int tid = threadIdx.x;
    const int w   = tid >> 5;
    const int l   = tid & 31;
    const int g   = l >> 2;
    const int tg  = l & 3;
    const int wm  = (w >> 1) * 32;
    const int wn  = (w & 1) * 64;
    const int m0  = blockIdx.y * 128;
    const int n0  = blockIdx.x * 128;

    const int mrow16 = (w >> 1) * 2;
    const int jpbase = (w & 1) * 4;

    const int l7 = l & 7, t4 = l >> 3;
    const uint32_t koff = ((((t4 >> 1) * 8 + l7) * 72) + (t4 & 1) * 8) * 2;
    const uint32_t qoff = ((((t4 & 1) * 8 + l7) * 72) + (t4 >> 1) * 8) * 2;

    auto stage = [&](int k0, int buf) {
        uint32_t au = base_u + (uint32_t)buf * 18432u;
        uint32_t wu = base_u + 36864u + (uint32_t)buf * 18432u;
        #pragma unroll
        for (int i = 0; i < 4; i++) {
            int ch  = tid + i * 256;
            int row = ch >> 3;
            int c   = (ch & 7) * 8;
            cp16(au + row * 144 + c * 2, g_Ah  + (size_t)(m0 + row) * DIN + k0 + c);
            cp16(wu + row * 144 + c * 2, g_Wot + (size_t)(n0 + row) * DIN + k0 + c);
        }
        CP_COMMIT();
    };

    float acc[2][8][4];
    #pragma unroll
    for (int mf = 0; mf < 2; mf++)
        #pragma unroll
        for (int j = 0; j < 8; j++)
            #pragma unroll
            for (int r = 0; r < 4; r++) acc[mf][j][r] = 0.0f;

    stage(0, 0);
    CP_WAIT0();
    __syncthreads();

    for (int kq = 0; kq < 8; kq++) {
        const int buf = kq & 1;
        if (kq + 1 < 8) stage((kq + 1) * 64, buf ^ 1);

        const uint32_t sA_u = base_u + (uint32_t)buf * 18432u;
        const uint32_t sW_u = base_u + 36864u + (uint32_t)buf * 18432u;

        #pragma unroll
        for (int ks = 0; ks < 4; ks++) {
            uint32_t a[2][4];
            #pragma unroll
            for (int mf = 0; mf < 2; mf++)
                ldsm_x4(sA_u + (1152 * (mrow16 + mf) + 16 * ks) * 2 + qoff,
                        a[mf][0], a[mf][1], a[mf][2], a[mf][3]);
            #pragma unroll
            for (int jp = 0; jp < 4; jp++) {
                uint32_t b0, b1, b2, b3;
                ldsm_x4(sW_u + (1152 * (jpbase + jp) + 16 * ks) * 2 + koff,
                        b0, b1, b2, b3);
                mma16816(acc[0][2 * jp    ], a[0][0], a[0][1], a[0][2], a[0][3], b0, b1);
                mma16816(acc[0][2 * jp + 1], a[0][0], a[0][1], a[0][2], a[0][3], b2, b3);
                mma16816(acc[1][2 * jp    ], a[1][0], a[1][1], a[1][2], a[1][3], b0, b1);
                mma16816(acc[1][2 * jp + 1], a[1][0], a[1][1], a[1][2], a[1][3], b2, b3);
            }
        }

        if (kq + 1 < 8) { CP_WAIT0(); __syncthreads(); }
    }

    #pragma unroll
    for (int mf = 0; mf < 2; mf++) {
        int row = m0 + wm + 16 * mf + g;
        #pragma unroll
        for (int j = 0; j < 8; j++) {
            int col = n0 + wn + 8 * j + 2 * tg;
            *(float2*)&out[(size_t)(row    ) * DIN + col] = make_float2(acc[mf][j][0], acc[mf][j][1]);
            *(float2*)&out[(size_t)(row + 8) * DIN + col] = make_float2(acc[mf][j][2], acc[mf][j][3]);
        }
    }
}

// ---------------------------------------------------------------------------
// Launch
// ---------------------------------------------------------------------------
extern "C" void kernel_launch(void* const* d_in, const int* in_sizes, int n_in,
                              void* d_out, int out_size)
{
    (void)in_sizes; (void)n_in; (void)out_size;
    const float* x  = (const float*)d_in[0];
    const float* Wq = (const float*)d_in[1];
    const float* Wk = (const float*)d_in[2];
    const float* Wv = (const float*)d_in[3];
    const float* Wo = (const float*)d_in[4];
    float* out = (float*)d_out;

    const int gemm_smem = 73728;   // 2 x (128x72 + 128x72) halves
    const int attn_smem = 82944;   // sQ + 4x sK + 4x sVt
    cudaFuncSetAttribute(qkv_hmma_kernel,
                         cudaFuncAttributeMaxDynamicSharedMemorySize, gemm_smem);
    cudaFuncSetAttribute(out_hmma_kernel,
                         cudaFuncAttributeMaxDynamicSharedMemorySize, gemm_smem);
    cudaFuncSetAttribute(attn_mma_kernel,
                         cudaFuncAttributeMaxDynamicSharedMemorySize, attn_smem);

    xcast_kernel<<<SEQ * DIN / 1024, 256>>>(x);
    wtrans_kernel<<<dim3(8, 8, 4), 256>>>(Wq, Wk, Wv, Wo);
    qkv_hmma_kernel<<<dim3(4, 32, 3), 256, gemm_smem>>>();
    attn_mma_kernel<<<dim3(32, HEADS), 256, attn_smem>>>();
    out_hmma_kernel<<<dim3(4, 32), 256, gemm_smem>>>(out);
}